// round 1
// baseline (speedup 1.0000x reference)
#include <cuda_runtime.h>

#define H 256
#define W 256
#define CIN 256
#define COMP 64
#define BATCH 4
#define HW (H * W)

// Scratch (device globals; no allocation allowed)
__device__ float g_comp[(size_t)BATCH * COMP * HW];   // 64 MiB
__device__ float g_s[(size_t)BATCH * 9 * HW];         // 9 MiB

// Packed fp32x2 FMA (sm_100+): d = a*b + c elementwise on pairs.
__device__ __forceinline__ float2 ffma2(float2 a, float2 b, float2 c) {
    unsigned long long au = *reinterpret_cast<unsigned long long*>(&a);
    unsigned long long bu = *reinterpret_cast<unsigned long long*>(&b);
    unsigned long long cu = *reinterpret_cast<unsigned long long*>(&c);
    unsigned long long du;
    asm("fma.rn.f32x2 %0, %1, %2, %3;" : "=l"(du) : "l"(au), "l"(bu), "l"(cu));
    return *reinterpret_cast<float2*>(&du);
}

// ---------------------------------------------------------------------------
// Kernel 1: 1x1 channel compression.  comp[b,o,p] = sum_c wc[o,c] * x[b,c,p]
// Block tile: 64 o x 128 p, 256 threads, 8 o x 4 p per thread (f32x2 pairs).
// ---------------------------------------------------------------------------
__global__ void __launch_bounds__(256) k_compress(const float* __restrict__ x,
                                                  const float* __restrict__ wc) {
    const int b  = blockIdx.y;
    const int p0 = blockIdx.x * 128;
    const float* xb = x + (size_t)b * CIN * HW;
    float* cb = g_comp + (size_t)b * COMP * HW;

    __shared__ float2 ws2[COMP][32];   // [o][c-chunk], pre-duplicated {w,w}: 16 KB
    __shared__ float  xs[32][128];     // [c-chunk][p]: 16 KB

    const int tid   = threadIdx.x;
    const int lane  = tid & 31;
    const int warp  = tid >> 5;        // 8 warps -> 8 o-groups
    const int obase = warp * 8;
    const int pl    = lane * 4;

    float2 acc[8][2];
#pragma unroll
    for (int o = 0; o < 8; o++) {
        acc[o][0] = make_float2(0.f, 0.f);
        acc[o][1] = make_float2(0.f, 0.f);
    }

    for (int c0 = 0; c0 < CIN; c0 += 32) {
        // Stage W chunk, duplicated for f32x2 (coalesced gmem read, seq smem store)
#pragma unroll
        for (int i = 0; i < 8; i++) {
            int idx = tid + i * 256;
            int oo = idx >> 5;
            int cc = idx & 31;
            float wv = wc[oo * CIN + c0 + cc];
            ws2[oo][cc] = make_float2(wv, wv);
        }
        // Stage x chunk via float4
#pragma unroll
        for (int i = 0; i < 4; i++) {
            int idx = (tid + i * 256) * 4;
            int cc = idx >> 7;
            int pp = idx & 127;
            *(float4*)&xs[cc][pp] =
                *(const float4*)(xb + (size_t)(c0 + cc) * HW + p0 + pp);
        }
        __syncthreads();
#pragma unroll 4
        for (int c = 0; c < 32; c++) {
            float4 xv = *(const float4*)&xs[c][pl];
            float2 xlo = make_float2(xv.x, xv.y);
            float2 xhi = make_float2(xv.z, xv.w);
#pragma unroll
            for (int o = 0; o < 8; o++) {
                float2 wv = ws2[obase + o][c];   // warp-broadcast LDS
                acc[o][0] = ffma2(xlo, wv, acc[o][0]);
                acc[o][1] = ffma2(xhi, wv, acc[o][1]);
            }
        }
        __syncthreads();
    }
#pragma unroll
    for (int o = 0; o < 8; o++) {
        float4 v = make_float4(acc[o][0].x, acc[o][0].y, acc[o][1].x, acc[o][1].y);
        *(float4*)(cb + (size_t)(obase + o) * HW + p0 + pl) = v;
    }
}

// ---------------------------------------------------------------------------
// Kernel 2: 3x3 conv (64 -> 9, zero pad) + bias + softmax over the 9 channels.
// Output layout (B, 9, H, W) contiguous.  Tile 64w x 8h, thread = 2 adjacent w.
// ---------------------------------------------------------------------------
__global__ void __launch_bounds__(256) k_convsoft(const float* __restrict__ wg,
                                                  const float* __restrict__ bg) {
    const int b  = blockIdx.z;
    const int h0 = blockIdx.y * 8;
    const int w0 = blockIdx.x * 64;

    __shared__ float  xs[8][10][68];    // [c][row][col] halo tile, 21.8 KB
    __shared__ float2 wg2[9][8][9];     // [kk][c][tap] duplicated, 5.2 KB

    const int tid = threadIdx.x;
    const int lh  = tid >> 5;
    const int lw  = (tid & 31) * 2;

    float2 acc[9];
#pragma unroll
    for (int kk = 0; kk < 9; kk++) {
        float bv = bg[kk];
        acc[kk] = make_float2(bv, bv);
    }

    const float* compb = g_comp + (size_t)b * COMP * HW;

    for (int c0 = 0; c0 < COMP; c0 += 8) {
        for (int idx = tid; idx < 9 * 8 * 9; idx += 256) {
            int kk = idx / 72;
            int rem = idx - kk * 72;
            int c = rem / 9;
            int tap = rem - c * 9;
            float v = wg[(kk * COMP + c0 + c) * 9 + tap];
            wg2[kk][c][tap] = make_float2(v, v);
        }
        for (int idx = tid; idx < 8 * 10 * 66; idx += 256) {
            int c = idx / 660;
            int rem = idx - c * 660;
            int r = rem / 66;
            int col = rem - r * 66;
            int gh = h0 + r - 1;
            int gw = w0 + col - 1;
            float v = 0.f;
            if ((unsigned)gh < 256u && (unsigned)gw < 256u)
                v = compb[(size_t)(c0 + c) * HW + gh * W + gw];
            xs[c][r][col] = v;
        }
        __syncthreads();
#pragma unroll
        for (int c = 0; c < 8; c++) {
#pragma unroll
            for (int di = 0; di < 3; di++) {
                float2 a  = *(const float2*)&xs[c][lh + di][lw];
                float2 b2 = *(const float2*)&xs[c][lh + di][lw + 2];
                float2 m  = make_float2(a.y, b2.x);
#pragma unroll
                for (int kk = 0; kk < 9; kk++) {
                    acc[kk] = ffma2(a,  wg2[kk][c][di * 3 + 0], acc[kk]);
                    acc[kk] = ffma2(m,  wg2[kk][c][di * 3 + 1], acc[kk]);
                    acc[kk] = ffma2(b2, wg2[kk][c][di * 3 + 2], acc[kk]);
                }
            }
        }
        __syncthreads();
    }

    // Softmax over kk per pixel
    float mA = acc[0].x, mB = acc[0].y;
#pragma unroll
    for (int kk = 1; kk < 9; kk++) {
        mA = fmaxf(mA, acc[kk].x);
        mB = fmaxf(mB, acc[kk].y);
    }
    float sA = 0.f, sB = 0.f;
#pragma unroll
    for (int kk = 0; kk < 9; kk++) {
        acc[kk].x = __expf(acc[kk].x - mA);
        acc[kk].y = __expf(acc[kk].y - mB);
        sA += acc[kk].x;
        sB += acc[kk].y;
    }
    float iA = 1.f / sA, iB = 1.f / sB;
    float* sb = g_s + (size_t)b * 9 * HW;
    const int pbase = (h0 + lh) * W + w0 + lw;
#pragma unroll
    for (int kk = 0; kk < 9; kk++) {
        *(float2*)(sb + (size_t)kk * HW + pbase) =
            make_float2(acc[kk].x * iA, acc[kk].y * iB);
    }
}

// ---------------------------------------------------------------------------
// Kernel 3: per-pixel weights (hamming * scrambled-view softmax, normalized)
// + reflect-padded 3x3 weighted aggregation.  out = 2x - agg.
// The .view reinterpret => pixel (h,w) weights are 9 CONSECUTIVE floats of g_s
// at flat offset (h*W+w)*9.
// ---------------------------------------------------------------------------
__global__ void __launch_bounds__(256) k_aggregate(const float* __restrict__ x,
                                                   float* __restrict__ out) {
    const int b  = blockIdx.z;
    const int h0 = blockIdx.y * 8;
    const int w0 = blockIdx.x * 64;

    __shared__ float xs[4][10][68];   // 4 channels staged per iter, 10.9 KB

    const int tid = threadIdx.x;
    const int lh  = tid >> 5;
    const int lw  = (tid & 31) * 2;
    const int h = h0 + lh, wcol = w0 + lw;

    // Per-pixel tap weights (two pixels per thread)
    const float* sp = g_s + (size_t)b * 9 * HW + (size_t)(h * W + wcol) * 9;
    const float HAM[9] = {0.0064f, 0.08f, 0.0064f,
                          0.08f,   1.0f,  0.08f,
                          0.0064f, 0.08f, 0.0064f};
    float wa[9], wb[9];
    float sa = 0.f, sb = 0.f;
#pragma unroll
    for (int t = 0; t < 9; t++) {
        wa[t] = HAM[t] * sp[t];     sa += wa[t];
        wb[t] = HAM[t] * sp[9 + t]; sb += wb[t];
    }
    float ia = 1.f / (sa + 1e-8f);
    float ib = 1.f / (sb + 1e-8f);
    float2 wt2[9];
#pragma unroll
    for (int t = 0; t < 9; t++) wt2[t] = make_float2(wa[t] * ia, wb[t] * ib);

    const float* xb = x + (size_t)b * CIN * HW;
    float* ob = out + (size_t)b * CIN * HW;

    for (int c0 = 0; c0 < CIN; c0 += 4) {
        for (int idx = tid; idx < 4 * 10 * 66; idx += 256) {
            int c = idx / 660;
            int rem = idx - c * 660;
            int r = rem / 66;
            int col = rem - r * 66;
            int gh = h0 + r - 1;
            if (gh < 0) gh = -gh; else if (gh > 255) gh = 510 - gh;   // reflect
            int gw = w0 + col - 1;
            if (gw < 0) gw = -gw; else if (gw > 255) gw = 510 - gw;
            xs[c][r][col] = xb[(size_t)(c0 + c) * HW + gh * W + gw];
        }
        __syncthreads();
#pragma unroll
        for (int c = 0; c < 4; c++) {
            float2 agg = make_float2(0.f, 0.f);
            float2 center = make_float2(0.f, 0.f);
#pragma unroll
            for (int di = 0; di < 3; di++) {
                float2 a  = *(const float2*)&xs[c][lh + di][lw];
                float2 b2 = *(const float2*)&xs[c][lh + di][lw + 2];
                float2 m  = make_float2(a.y, b2.x);
                agg = ffma2(a,  wt2[di * 3 + 0], agg);
                agg = ffma2(m,  wt2[di * 3 + 1], agg);
                agg = ffma2(b2, wt2[di * 3 + 2], agg);
                if (di == 1) center = m;
            }
            float2 o2 = make_float2(2.f * center.x - agg.x,
                                    2.f * center.y - agg.y);
            *(float2*)(ob + (size_t)(c0 + c) * HW + h * W + wcol) = o2;
        }
        __syncthreads();
    }
}

// ---------------------------------------------------------------------------
extern "C" void kernel_launch(void* const* d_in, const int* in_sizes, int n_in,
                              void* d_out, int out_size) {
    const float* x  = (const float*)d_in[0];   // (4,256,256,256)
    const float* wc = (const float*)d_in[1];   // (64,256)
    const float* wg = (const float*)d_in[2];   // (9,64,3,3)
    const float* bg = (const float*)d_in[3];   // (9,)
    float* out = (float*)d_out;

    k_compress <<<dim3(HW / 128, BATCH), 256>>>(x, wc);
    k_convsoft <<<dim3(W / 64, H / 8, BATCH), 256>>>(wg, bg);
    k_aggregate<<<dim3(W / 64, H / 8, BATCH), 256>>>(x, out);
}

// round 3
// speedup vs baseline: 1.1300x; 1.1300x over previous
#include <cuda_runtime.h>
#include <cstdint>

#define H 256
#define W 256
#define CIN 256
#define COMP 64
#define BATCH 4
#define HW (H * W)

// Scratch (device globals; no allocation allowed)
__device__ float g_comp[(size_t)BATCH * COMP * HW];   // 64 MiB
__device__ float g_s[(size_t)BATCH * 9 * HW];         // 9 MiB

// Packed fp32x2 FMA (sm_100+): d = a*b + c elementwise on pairs.
__device__ __forceinline__ float2 ffma2(float2 a, float2 b, float2 c) {
    unsigned long long au = *reinterpret_cast<unsigned long long*>(&a);
    unsigned long long bu = *reinterpret_cast<unsigned long long*>(&b);
    unsigned long long cu = *reinterpret_cast<unsigned long long*>(&c);
    unsigned long long du;
    asm("fma.rn.f32x2 %0, %1, %2, %3;" : "=l"(du) : "l"(au), "l"(bu), "l"(cu));
    return *reinterpret_cast<float2*>(&du);
}

__device__ __forceinline__ void cp_async4(uint32_t dst_smem, const float* src) {
    asm volatile("cp.async.ca.shared.global [%0], [%1], 4;"
                 :: "r"(dst_smem), "l"(src) : "memory");
}

// ---------------------------------------------------------------------------
// Kernel 1: 1x1 channel compression.  comp[b,o,p] = sum_c wc[o,c] * x[b,c,p]
// Block tile: 64 o x 256 p, 256 threads, 8 o x 8 p per thread.
// Per c: 2 LDS.128 + 8 LDS.64 for 32 FFMA2  -> FMA-bound.
// ---------------------------------------------------------------------------
__global__ void __launch_bounds__(256) k_compress(const float* __restrict__ x,
                                                  const float* __restrict__ wc) {
    const int b  = blockIdx.y;
    const int p0 = blockIdx.x * 256;
    const float* xb = x + (size_t)b * CIN * HW;
    float* cb = g_comp + (size_t)b * COMP * HW;

    __shared__ float2 ws2[COMP][32];   // 16 KB, duplicated {w,w}
    __shared__ float  xs[32][256];     // 32 KB

    const int tid   = threadIdx.x;
    const int lane  = tid & 31;
    const int warp  = tid >> 5;        // 8 warps -> 8 o-groups
    const int obase = warp * 8;
    const int pl    = lane * 8;

    float2 acc[8][4];
#pragma unroll
    for (int o = 0; o < 8; o++)
#pragma unroll
        for (int q = 0; q < 4; q++) acc[o][q] = make_float2(0.f, 0.f);

    for (int c0 = 0; c0 < CIN; c0 += 32) {
        // Stage W chunk (2048 floats)
#pragma unroll
        for (int i = 0; i < 8; i++) {
            int idx = tid + i * 256;
            int oo = idx >> 5;
            int cc = idx & 31;
            float wv = wc[oo * CIN + c0 + cc];
            ws2[oo][cc] = make_float2(wv, wv);
        }
        // Stage x chunk (8192 floats) via float4
#pragma unroll
        for (int i = 0; i < 8; i++) {
            int idx = (tid + i * 256) * 4;
            int cc = idx >> 8;
            int pp = idx & 255;
            *(float4*)&xs[cc][pp] =
                *(const float4*)(xb + (size_t)(c0 + cc) * HW + p0 + pp);
        }
        __syncthreads();
#pragma unroll 4
        for (int c = 0; c < 32; c++) {
            float4 xa = *(const float4*)&xs[c][pl];
            float4 xc = *(const float4*)&xs[c][pl + 4];
            float2 x0 = make_float2(xa.x, xa.y);
            float2 x1 = make_float2(xa.z, xa.w);
            float2 x2 = make_float2(xc.x, xc.y);
            float2 x3 = make_float2(xc.z, xc.w);
#pragma unroll
            for (int o = 0; o < 8; o++) {
                float2 wv = ws2[obase + o][c];   // warp-broadcast LDS
                acc[o][0] = ffma2(x0, wv, acc[o][0]);
                acc[o][1] = ffma2(x1, wv, acc[o][1]);
                acc[o][2] = ffma2(x2, wv, acc[o][2]);
                acc[o][3] = ffma2(x3, wv, acc[o][3]);
            }
        }
        __syncthreads();
    }
#pragma unroll
    for (int o = 0; o < 8; o++) {
        float* dst = cb + (size_t)(obase + o) * HW + p0 + pl;
        *(float4*)dst       = make_float4(acc[o][0].x, acc[o][0].y,
                                          acc[o][1].x, acc[o][1].y);
        *(float4*)(dst + 4) = make_float4(acc[o][2].x, acc[o][2].y,
                                          acc[o][3].x, acc[o][3].y);
    }
}

// ---------------------------------------------------------------------------
// Kernel 2: 3x3 conv (64 -> 9, zero pad) + bias + softmax over the 9 channels.
// Output layout (B, 9, H, W) contiguous.  Tile 64w x 8h, thread = 2 adjacent w.
// ---------------------------------------------------------------------------
__global__ void __launch_bounds__(256) k_convsoft(const float* __restrict__ wg,
                                                  const float* __restrict__ bg) {
    const int b  = blockIdx.z;
    const int h0 = blockIdx.y * 8;
    const int w0 = blockIdx.x * 64;

    __shared__ float  xs[8][10][68];    // halo tile, 21.8 KB
    __shared__ float2 wg2[9][8][9];     // duplicated, 5.2 KB

    const int tid = threadIdx.x;
    const int lh  = tid >> 5;
    const int lw  = (tid & 31) * 2;

    float2 acc[9];
#pragma unroll
    for (int kk = 0; kk < 9; kk++) {
        float bv = bg[kk];
        acc[kk] = make_float2(bv, bv);
    }

    const float* compb = g_comp + (size_t)b * COMP * HW;

    for (int c0 = 0; c0 < COMP; c0 += 8) {
        for (int idx = tid; idx < 9 * 8 * 9; idx += 256) {
            int kk = idx / 72;
            int rem = idx - kk * 72;
            int c = rem / 9;
            int tap = rem - c * 9;
            float v = wg[(kk * COMP + c0 + c) * 9 + tap];
            wg2[kk][c][tap] = make_float2(v, v);
        }
        for (int idx = tid; idx < 8 * 10 * 66; idx += 256) {
            int c = idx / 660;
            int rem = idx - c * 660;
            int r = rem / 66;
            int col = rem - r * 66;
            int gh = h0 + r - 1;
            int gw = w0 + col - 1;
            float v = 0.f;
            if ((unsigned)gh < 256u && (unsigned)gw < 256u)
                v = compb[(size_t)(c0 + c) * HW + gh * W + gw];
            xs[c][r][col] = v;
        }
        __syncthreads();
#pragma unroll
        for (int c = 0; c < 8; c++) {
#pragma unroll
            for (int di = 0; di < 3; di++) {
                float2 a  = *(const float2*)&xs[c][lh + di][lw];
                float2 b2 = *(const float2*)&xs[c][lh + di][lw + 2];
                float2 m  = make_float2(a.y, b2.x);
#pragma unroll
                for (int kk = 0; kk < 9; kk++) {
                    acc[kk] = ffma2(a,  wg2[kk][c][di * 3 + 0], acc[kk]);
                    acc[kk] = ffma2(m,  wg2[kk][c][di * 3 + 1], acc[kk]);
                    acc[kk] = ffma2(b2, wg2[kk][c][di * 3 + 2], acc[kk]);
                }
            }
        }
        __syncthreads();
    }

    // Softmax over kk per pixel
    float mA = acc[0].x, mB = acc[0].y;
#pragma unroll
    for (int kk = 1; kk < 9; kk++) {
        mA = fmaxf(mA, acc[kk].x);
        mB = fmaxf(mB, acc[kk].y);
    }
    float sA = 0.f, sB = 0.f;
#pragma unroll
    for (int kk = 0; kk < 9; kk++) {
        acc[kk].x = __expf(acc[kk].x - mA);
        acc[kk].y = __expf(acc[kk].y - mB);
        sA += acc[kk].x;
        sB += acc[kk].y;
    }
    float iA = 1.f / sA, iB = 1.f / sB;
    float* sb = g_s + (size_t)b * 9 * HW;
    const int pbase = (h0 + lh) * W + w0 + lw;
#pragma unroll
    for (int kk = 0; kk < 9; kk++) {
        *(float2*)(sb + (size_t)kk * HW + pbase) =
            make_float2(acc[kk].x * iA, acc[kk].y * iB);
    }
}

// ---------------------------------------------------------------------------
// Kernel 3: per-pixel weights (hamming * scrambled-view softmax, normalized)
// + reflect-padded 3x3 weighted aggregation.  out = 2x - agg.
// Channel dim split across blocks (64 ch per block), 8-channel chunks,
// cp.async double-buffered staging.
// ---------------------------------------------------------------------------
#define K3_CH 8           // channels per chunk
#define K3_CHUNKS 8       // chunks per block (64 channels)

__global__ void __launch_bounds__(256) k_aggregate(const float* __restrict__ x,
                                                   float* __restrict__ out) {
    const int bz = blockIdx.z;
    const int b  = bz >> 2;
    const int cg = bz & 3;              // channel group: 64 channels
    const int h0 = blockIdx.y * 8;
    const int w0 = blockIdx.x * 64;

    __shared__ float xs[2][K3_CH][10][68];   // 2 x 21.8 KB

    const int tid = threadIdx.x;
    const int lh  = tid >> 5;
    const int lw  = (tid & 31) * 2;
    const int h = h0 + lh, wcol = w0 + lw;

    // Per-pixel tap weights (two pixels per thread)
    const float* sp = g_s + (size_t)b * 9 * HW + (size_t)(h * W + wcol) * 9;
    const float HAM[9] = {0.0064f, 0.08f, 0.0064f,
                          0.08f,   1.0f,  0.08f,
                          0.0064f, 0.08f, 0.0064f};
    float wa[9], wb[9];
    float sa = 0.f, sb = 0.f;
#pragma unroll
    for (int t = 0; t < 9; t++) {
        wa[t] = HAM[t] * sp[t];     sa += wa[t];
        wb[t] = HAM[t] * sp[9 + t]; sb += wb[t];
    }
    float ia = 1.f / (sa + 1e-8f);
    float ib = 1.f / (sb + 1e-8f);
    float2 wt2[9];
#pragma unroll
    for (int t = 0; t < 9; t++) wt2[t] = make_float2(wa[t] * ia, wb[t] * ib);

    const float* xb = x + ((size_t)b * CIN + cg * 64) * HW;
    float* ob = out + ((size_t)b * CIN + cg * 64) * HW;

    const uint32_t smem_base =
        (uint32_t)__cvta_generic_to_shared(&xs[0][0][0][0]);

    // Stage one 8-channel chunk via cp.async
    auto stage = [&](int buf, int chunk) {
        const float* src_base = xb + (size_t)chunk * K3_CH * HW;
        uint32_t dbase = smem_base + buf * (K3_CH * 10 * 68 * 4);
        for (int idx = tid; idx < K3_CH * 10 * 66; idx += 256) {
            int c = idx / 660;
            int rem = idx - c * 660;
            int r = rem / 66;
            int col = rem - r * 66;
            int gh = h0 + r - 1;
            if (gh < 0) gh = -gh; else if (gh > 255) gh = 510 - gh;   // reflect
            int gw = w0 + col - 1;
            if (gw < 0) gw = -gw; else if (gw > 255) gw = 510 - gw;
            cp_async4(dbase + (uint32_t)(((c * 10 + r) * 68 + col) * 4),
                      src_base + (size_t)c * HW + gh * W + gw);
        }
        asm volatile("cp.async.commit_group;" ::: "memory");
    };

    stage(0, 0);

    for (int chunk = 0; chunk < K3_CHUNKS; chunk++) {
        const int cur = chunk & 1;
        if (chunk + 1 < K3_CHUNKS) {
            stage(cur ^ 1, chunk + 1);
            asm volatile("cp.async.wait_group 1;" ::: "memory");
        } else {
            asm volatile("cp.async.wait_group 0;" ::: "memory");
        }
        __syncthreads();

        float* ochunk = ob + (size_t)chunk * K3_CH * HW + h * W + wcol;
#pragma unroll
        for (int c = 0; c < K3_CH; c++) {
            float2 agg = make_float2(0.f, 0.f);
            float2 center = make_float2(0.f, 0.f);
#pragma unroll
            for (int di = 0; di < 3; di++) {
                float2 a  = *(const float2*)&xs[cur][c][lh + di][lw];
                float2 b2 = *(const float2*)&xs[cur][c][lh + di][lw + 2];
                float2 m  = make_float2(a.y, b2.x);
                agg = ffma2(a,  wt2[di * 3 + 0], agg);
                agg = ffma2(m,  wt2[di * 3 + 1], agg);
                agg = ffma2(b2, wt2[di * 3 + 2], agg);
                if (di == 1) center = m;
            }
            float2 o2 = make_float2(2.f * center.x - agg.x,
                                    2.f * center.y - agg.y);
            *(float2*)(ochunk + (size_t)c * HW) = o2;
        }
        __syncthreads();
    }
}

// ---------------------------------------------------------------------------
extern "C" void kernel_launch(void* const* d_in, const int* in_sizes, int n_in,
                              void* d_out, int out_size) {
    const float* x  = (const float*)d_in[0];   // (4,256,256,256)
    const float* wc = (const float*)d_in[1];   // (64,256)
    const float* wg = (const float*)d_in[2];   // (9,64,3,3)
    const float* bg = (const float*)d_in[3];   // (9,)
    float* out = (float*)d_out;

    k_compress <<<dim3(HW / 256, BATCH), 256>>>(x, wc);
    k_convsoft <<<dim3(W / 64, H / 8, BATCH), 256>>>(wg, bg);
    k_aggregate<<<dim3(W / 64, H / 8, BATCH * 4), 256>>>(x, out);
}

// round 4
// speedup vs baseline: 1.3896x; 1.2297x over previous
#include <cuda_runtime.h>
#include <cstdint>

#define H 256
#define W 256
#define CIN 256
#define COMP 64
#define BATCH 4
#define HW (H * W)

__device__ float g_comp[(size_t)BATCH * COMP * HW];   // 64 MiB
__device__ float g_s[(size_t)BATCH * 9 * HW];         // 9 MiB

__device__ __forceinline__ float2 ffma2(float2 a, float2 b, float2 c) {
    unsigned long long au = *reinterpret_cast<unsigned long long*>(&a);
    unsigned long long bu = *reinterpret_cast<unsigned long long*>(&b);
    unsigned long long cu = *reinterpret_cast<unsigned long long*>(&c);
    unsigned long long du;
    asm("fma.rn.f32x2 %0, %1, %2, %3;" : "=l"(du) : "l"(au), "l"(bu), "l"(cu));
    return *reinterpret_cast<float2*>(&du);
}

__device__ __forceinline__ void cp_async4(uint32_t dst_smem, const float* src) {
    asm volatile("cp.async.ca.shared.global [%0], [%1], 4;"
                 :: "r"(dst_smem), "l"(src) : "memory");
}

// ---------------------------------------------------------------------------
// Kernel 1: 1x1 compression. Pair dim = adjacent o (weights packed by LDS.128).
// Block 64 o x 128 p, 256 thr, thread = 4 o-pairs x 4 p.
// Per c per thread: 1 LDS.128(x) + 2 LDS.128(w, broadcast) + 4 MOV + 16 FFMA2.
// ---------------------------------------------------------------------------
__global__ void __launch_bounds__(256) k_compress(const float* __restrict__ x,
                                                  const float* __restrict__ wc) {
    const int b  = blockIdx.y;
    const int p0 = blockIdx.x * 128;
    const float* xb = x + (size_t)b * CIN * HW;
    float* cb = g_comp + (size_t)b * COMP * HW;

    __shared__ float ws[32][68];    // [c][o] plain, pad 68 (stage conflicts 4-way)
    __shared__ float xs[32][128];   // [c][p]

    const int tid   = threadIdx.x;
    const int lane  = tid & 31;
    const int warp  = tid >> 5;
    const int obase = warp * 8;     // 8 o per warp-group of threads
    const int pl    = lane * 4;

    float2 acc[4][4];               // [o-pair][p]
#pragma unroll
    for (int op = 0; op < 4; op++)
#pragma unroll
        for (int p = 0; p < 4; p++) acc[op][p] = make_float2(0.f, 0.f);

    for (int c0 = 0; c0 < CIN; c0 += 32) {
        // Stage W chunk transposed to [c][o] (coalesced gmem reads)
#pragma unroll
        for (int i = 0; i < 8; i++) {
            int idx = tid + i * 256;
            int oo = idx >> 5;
            int cc = idx & 31;
            ws[cc][oo] = wc[oo * CIN + c0 + cc];
        }
        // Stage x chunk via float4
#pragma unroll
        for (int i = 0; i < 4; i++) {
            int idx = (tid + i * 256) * 4;
            int cc = idx >> 7;
            int pp = idx & 127;
            *(float4*)&xs[cc][pp] =
                *(const float4*)(xb + (size_t)(c0 + cc) * HW + p0 + pp);
        }
        __syncthreads();
#pragma unroll 4
        for (int c = 0; c < 32; c++) {
            float4 xv = *(const float4*)&xs[c][pl];
            float2 xd[4];
            xd[0] = make_float2(xv.x, xv.x);
            xd[1] = make_float2(xv.y, xv.y);
            xd[2] = make_float2(xv.z, xv.z);
            xd[3] = make_float2(xv.w, xv.w);
            float4 wA = *(const float4*)&ws[c][obase];      // broadcast
            float4 wB = *(const float4*)&ws[c][obase + 4];  // broadcast
            float2 wp[4];
            wp[0] = make_float2(wA.x, wA.y);
            wp[1] = make_float2(wA.z, wA.w);
            wp[2] = make_float2(wB.x, wB.y);
            wp[3] = make_float2(wB.z, wB.w);
#pragma unroll
            for (int op = 0; op < 4; op++)
#pragma unroll
                for (int p = 0; p < 4; p++)
                    acc[op][p] = ffma2(xd[p], wp[op], acc[op][p]);
        }
        __syncthreads();
    }
#pragma unroll
    for (int op = 0; op < 4; op++) {
        float* d0 = cb + (size_t)(obase + 2 * op) * HW + p0 + pl;
        *(float4*)d0 = make_float4(acc[op][0].x, acc[op][1].x,
                                   acc[op][2].x, acc[op][3].x);
        *(float4*)(d0 + HW) = make_float4(acc[op][0].y, acc[op][1].y,
                                          acc[op][2].y, acc[op][3].y);
    }
}

// ---------------------------------------------------------------------------
// Kernel 2: 3x3 conv (64->9, zero pad) + bias + softmax over 9 channels.
// Pair dim = adjacent kk (weights packed [c][tap][12], kk-major, zero pad).
// Tile 64w x 8h, 256 thr, thread = 2 adjacent pixels.
// Per c per thread: 6 LDS.64(x) + 27 LDS.128(w, bcast) + 12 MOV + 90 FFMA2.
// ---------------------------------------------------------------------------
__global__ void __launch_bounds__(256) k_convsoft(const float* __restrict__ wg,
                                                  const float* __restrict__ bg) {
    const int b  = blockIdx.z;
    const int h0 = blockIdx.y * 8;
    const int w0 = blockIdx.x * 64;

    __shared__ float xs[8][10][68];     // halo tile, 21.8 KB
    __shared__ float wgs[8][9][12];     // [c][tap][kk pad12], 3.5 KB

    const int tid = threadIdx.x;
    const int lh  = tid >> 5;
    const int lw  = (tid & 31) * 2;

    // acc[px][kkpair]: 10 kk (kk9 = pad)
    float2 acc[2][5];
#pragma unroll
    for (int j = 0; j < 5; j++) {
        float blo = bg[2 * j];
        float bhi = (2 * j + 1 < 9) ? bg[2 * j + 1] : 0.f;
        acc[0][j] = make_float2(blo, bhi);
        acc[1][j] = make_float2(blo, bhi);
    }

    const float* compb = g_comp + (size_t)b * COMP * HW;

    for (int c0 = 0; c0 < COMP; c0 += 8) {
        // weights: wgs[c][tap][kk] = wg[(kk*COMP + c0+c)*9 + tap], kk<9 else 0
        for (int idx = tid; idx < 8 * 9 * 12; idx += 256) {
            int c = idx / 108;
            int rem = idx - c * 108;
            int tap = rem / 12;
            int q = rem - tap * 12;
            float v = 0.f;
            if (q < 9) v = wg[(q * COMP + c0 + c) * 9 + tap];
            wgs[c][tap][q] = v;
        }
        for (int idx = tid; idx < 8 * 10 * 66; idx += 256) {
            int c = idx / 660;
            int rem = idx - c * 660;
            int r = rem / 66;
            int col = rem - r * 66;
            int gh = h0 + r - 1;
            int gw = w0 + col - 1;
            float v = 0.f;
            if ((unsigned)gh < 256u && (unsigned)gw < 256u)
                v = compb[(size_t)(c0 + c) * HW + gh * W + gw];
            xs[c][r][col] = v;
        }
        __syncthreads();
#pragma unroll
        for (int c = 0; c < 8; c++) {
#pragma unroll
            for (int di = 0; di < 3; di++) {
                float2 a  = *(const float2*)&xs[c][lh + di][lw];
                float2 b2 = *(const float2*)&xs[c][lh + di][lw + 2];
                float2 d[4];
                d[0] = make_float2(a.x, a.x);
                d[1] = make_float2(a.y, a.y);
                d[2] = make_float2(b2.x, b2.x);
                d[3] = make_float2(b2.y, b2.y);
#pragma unroll
                for (int tap = 0; tap < 3; tap++) {
                    const float* wrow = &wgs[c][di * 3 + tap][0];
                    float4 w0 = *(const float4*)(wrow);      // kk 0-3
                    float4 w1 = *(const float4*)(wrow + 4);  // kk 4-7
                    float4 w2 = *(const float4*)(wrow + 8);  // kk 8-11
                    float2 wq[5];
                    wq[0] = make_float2(w0.x, w0.y);
                    wq[1] = make_float2(w0.z, w0.w);
                    wq[2] = make_float2(w1.x, w1.y);
                    wq[3] = make_float2(w1.z, w1.w);
                    wq[4] = make_float2(w2.x, w2.y);
                    // px0 uses tap value d[tap], px1 uses d[tap+1]
#pragma unroll
                    for (int j = 0; j < 5; j++) {
                        acc[0][j] = ffma2(d[tap],     wq[j], acc[0][j]);
                        acc[1][j] = ffma2(d[tap + 1], wq[j], acc[1][j]);
                    }
                }
            }
        }
        __syncthreads();
    }

    // Softmax over 9 kk per pixel (kk9 pad excluded)
    float v0[9], v1[9];
#pragma unroll
    for (int j = 0; j < 5; j++) {
        v0[2 * j] = acc[0][j].x;  v1[2 * j] = acc[1][j].x;
        if (2 * j + 1 < 9) { v0[2 * j + 1] = acc[0][j].y; v1[2 * j + 1] = acc[1][j].y; }
    }
    float mA = v0[0], mB = v1[0];
#pragma unroll
    for (int kk = 1; kk < 9; kk++) { mA = fmaxf(mA, v0[kk]); mB = fmaxf(mB, v1[kk]); }
    float sA = 0.f, sB = 0.f;
#pragma unroll
    for (int kk = 0; kk < 9; kk++) {
        v0[kk] = __expf(v0[kk] - mA); sA += v0[kk];
        v1[kk] = __expf(v1[kk] - mB); sB += v1[kk];
    }
    float iA = 1.f / sA, iB = 1.f / sB;
    float* sb = g_s + (size_t)b * 9 * HW;
    const int pbase = (h0 + lh) * W + w0 + lw;
#pragma unroll
    for (int kk = 0; kk < 9; kk++)
        *(float2*)(sb + (size_t)kk * HW + pbase) =
            make_float2(v0[kk] * iA, v1[kk] * iB);
}

// ---------------------------------------------------------------------------
// Kernel 3: per-pixel weights + reflect-padded 3x3 aggregation. out = 2x - agg.
// Channel-split grid (64 ch/block), cp.async double-buffered.
// ---------------------------------------------------------------------------
#define K3_CH 8
#define K3_CHUNKS 8

__global__ void __launch_bounds__(256) k_aggregate(const float* __restrict__ x,
                                                   float* __restrict__ out) {
    const int bz = blockIdx.z;
    const int b  = bz >> 2;
    const int cg = bz & 3;
    const int h0 = blockIdx.y * 8;
    const int w0 = blockIdx.x * 64;

    __shared__ float xs[2][K3_CH][10][68];

    const int tid = threadIdx.x;
    const int lh  = tid >> 5;
    const int lw  = (tid & 31) * 2;
    const int h = h0 + lh, wcol = w0 + lw;

    const float* sp = g_s + (size_t)b * 9 * HW + (size_t)(h * W + wcol) * 9;
    const float HAM[9] = {0.0064f, 0.08f, 0.0064f,
                          0.08f,   1.0f,  0.08f,
                          0.0064f, 0.08f, 0.0064f};
    float wa[9], wb[9];
    float sa = 0.f, sb = 0.f;
#pragma unroll
    for (int t = 0; t < 9; t++) {
        wa[t] = HAM[t] * sp[t];     sa += wa[t];
        wb[t] = HAM[t] * sp[9 + t]; sb += wb[t];
    }
    float ia = 1.f / (sa + 1e-8f);
    float ib = 1.f / (sb + 1e-8f);
    float2 wt2[9];
#pragma unroll
    for (int t = 0; t < 9; t++) wt2[t] = make_float2(wa[t] * ia, wb[t] * ib);

    const float* xb = x + ((size_t)b * CIN + cg * 64) * HW;
    float* ob = out + ((size_t)b * CIN + cg * 64) * HW;

    const uint32_t smem_base =
        (uint32_t)__cvta_generic_to_shared(&xs[0][0][0][0]);

    auto stage = [&](int buf, int chunk) {
        const float* src_base = xb + (size_t)chunk * K3_CH * HW;
        uint32_t dbase = smem_base + buf * (K3_CH * 10 * 68 * 4);
        for (int idx = tid; idx < K3_CH * 10 * 66; idx += 256) {
            int c = idx / 660;
            int rem = idx - c * 660;
            int r = rem / 66;
            int col = rem - r * 66;
            int gh = h0 + r - 1;
            if (gh < 0) gh = -gh; else if (gh > 255) gh = 510 - gh;
            int gw = w0 + col - 1;
            if (gw < 0) gw = -gw; else if (gw > 255) gw = 510 - gw;
            cp_async4(dbase + (uint32_t)(((c * 10 + r) * 68 + col) * 4),
                      src_base + (size_t)c * HW + gh * W + gw);
        }
        asm volatile("cp.async.commit_group;" ::: "memory");
    };

    stage(0, 0);

    for (int chunk = 0; chunk < K3_CHUNKS; chunk++) {
        const int cur = chunk & 1;
        if (chunk + 1 < K3_CHUNKS) {
            stage(cur ^ 1, chunk + 1);
            asm volatile("cp.async.wait_group 1;" ::: "memory");
        } else {
            asm volatile("cp.async.wait_group 0;" ::: "memory");
        }
        __syncthreads();

        float* ochunk = ob + (size_t)chunk * K3_CH * HW + h * W + wcol;
#pragma unroll
        for (int c = 0; c < K3_CH; c++) {
            float2 agg = make_float2(0.f, 0.f);
            float2 center = make_float2(0.f, 0.f);
#pragma unroll
            for (int di = 0; di < 3; di++) {
                float2 a  = *(const float2*)&xs[cur][c][lh + di][lw];
                float2 b2 = *(const float2*)&xs[cur][c][lh + di][lw + 2];
                float2 m  = make_float2(a.y, b2.x);
                agg = ffma2(a,  wt2[di * 3 + 0], agg);
                agg = ffma2(m,  wt2[di * 3 + 1], agg);
                agg = ffma2(b2, wt2[di * 3 + 2], agg);
                if (di == 1) center = m;
            }
            float2 o2 = make_float2(2.f * center.x - agg.x,
                                    2.f * center.y - agg.y);
            *(float2*)(ochunk + (size_t)c * HW) = o2;
        }
        __syncthreads();
    }
}

// ---------------------------------------------------------------------------
extern "C" void kernel_launch(void* const* d_in, const int* in_sizes, int n_in,
                              void* d_out, int out_size) {
    const float* x  = (const float*)d_in[0];
    const float* wc = (const float*)d_in[1];
    const float* wg = (const float*)d_in[2];
    const float* bg = (const float*)d_in[3];
    float* out = (float*)d_out;

    k_compress <<<dim3(HW / 128, BATCH), 256>>>(x, wc);
    k_convsoft <<<dim3(W / 64, H / 8, BATCH), 256>>>(wg, bg);
    k_aggregate<<<dim3(W / 64, H / 8, BATCH * 4), 256>>>(x, out);
}

// round 5
// speedup vs baseline: 1.4642x; 1.0537x over previous
#include <cuda_runtime.h>
#include <cstdint>

#define H 256
#define W 256
#define CIN 256
#define COMP 64
#define BATCH 4
#define HW (H * W)

__device__ float g_comp[(size_t)BATCH * COMP * HW];   // 64 MiB
__device__ float g_s[(size_t)BATCH * 9 * HW];         // 9 MiB
__device__ float g_wt[CIN * COMP];                    // W transposed [c][o]

__device__ __forceinline__ float2 ffma2(float2 a, float2 b, float2 c) {
    unsigned long long au = *reinterpret_cast<unsigned long long*>(&a);
    unsigned long long bu = *reinterpret_cast<unsigned long long*>(&b);
    unsigned long long cu = *reinterpret_cast<unsigned long long*>(&c);
    unsigned long long du;
    asm("fma.rn.f32x2 %0, %1, %2, %3;" : "=l"(du) : "l"(au), "l"(bu), "l"(cu));
    return *reinterpret_cast<float2*>(&du);
}

__device__ __forceinline__ void cp_async16(uint32_t dst, const float* src) {
    asm volatile("cp.async.ca.shared.global [%0], [%1], 16;"
                 :: "r"(dst), "l"(src) : "memory");
}
__device__ __forceinline__ void cp_async4(uint32_t dst, const float* src) {
    asm volatile("cp.async.ca.shared.global [%0], [%1], 4;"
                 :: "r"(dst), "l"(src) : "memory");
}
// zero-fill variant: src_sz = 0 -> writes 4 zero bytes
__device__ __forceinline__ void cp_async4z(uint32_t dst, const float* src, int src_sz) {
    asm volatile("cp.async.ca.shared.global [%0], [%1], 4, %2;"
                 :: "r"(dst), "l"(src), "r"(src_sz) : "memory");
}
#define CP_COMMIT() asm volatile("cp.async.commit_group;" ::: "memory")
#define CP_WAIT(n)  asm volatile("cp.async.wait_group %0;" :: "n"(n) : "memory")

// ---------------------------------------------------------------------------
// Kernel 0: transpose wc (64x256) -> g_wt (256x64)
// ---------------------------------------------------------------------------
__global__ void k_wt(const float* __restrict__ wc) {
    int e = blockIdx.x * 256 + threadIdx.x;   // 16384 elems, grid 64
    int o = e >> 8, c = e & 255;
    g_wt[c * COMP + o] = wc[e];
}

// ---------------------------------------------------------------------------
// Kernel 1: 1x1 compression, cp.async double-buffered.
// Block 64 o x 128 p, 256 thr, thread = 4 o-pairs x 4 p.
// ---------------------------------------------------------------------------
__global__ void __launch_bounds__(256) k_compress(const float* __restrict__ x) {
    const int b  = blockIdx.y;
    const int p0 = blockIdx.x * 128;
    const float* xb = x + (size_t)b * CIN * HW;
    float* cb = g_comp + (size_t)b * COMP * HW;

    __shared__ float ws[2][32][64];    // [buf][c][o]
    __shared__ float xs[2][32][128];   // [buf][c][p]

    const int tid   = threadIdx.x;
    const int lane  = tid & 31;
    const int warp  = tid >> 5;
    const int obase = warp * 8;
    const int pl    = lane * 4;

    const uint32_t ws_base = (uint32_t)__cvta_generic_to_shared(&ws[0][0][0]);
    const uint32_t xs_base = (uint32_t)__cvta_generic_to_shared(&xs[0][0][0]);

    auto stage = [&](int buf, int c0) {
        // x chunk: 32c x 128p = 1024 float4, 4 per thread
#pragma unroll
        for (int i = 0; i < 4; i++) {
            int idx = tid + i * 256;       // float4 index
            int cc = idx >> 5;             // 32 f4 per row
            int k  = idx & 31;
            cp_async16(xs_base + (uint32_t)(buf * 32 * 128 + cc * 128 + k * 4) * 4,
                       xb + (size_t)(c0 + cc) * HW + p0 + k * 4);
        }
        // w chunk: 32c x 64o = 512 float4, 2 per thread (contiguous in g_wt)
#pragma unroll
        for (int i = 0; i < 2; i++) {
            int idx = tid + i * 256;
            int cc = idx >> 4;             // 16 f4 per row
            int k  = idx & 15;
            cp_async16(ws_base + (uint32_t)(buf * 32 * 64 + cc * 64 + k * 4) * 4,
                       g_wt + (c0 + cc) * COMP + k * 4);
        }
        CP_COMMIT();
    };

    float2 acc[4][4];
#pragma unroll
    for (int op = 0; op < 4; op++)
#pragma unroll
        for (int p = 0; p < 4; p++) acc[op][p] = make_float2(0.f, 0.f);

    stage(0, 0);

    for (int it = 0; it < 8; it++) {
        const int cur = it & 1;
        if (it + 1 < 8) { stage(cur ^ 1, (it + 1) * 32); CP_WAIT(1); }
        else            { CP_WAIT(0); }
        __syncthreads();
#pragma unroll 4
        for (int c = 0; c < 32; c++) {
            float4 xv = *(const float4*)&xs[cur][c][pl];
            float2 xd[4];
            xd[0] = make_float2(xv.x, xv.x);
            xd[1] = make_float2(xv.y, xv.y);
            xd[2] = make_float2(xv.z, xv.z);
            xd[3] = make_float2(xv.w, xv.w);
            float4 wA = *(const float4*)&ws[cur][c][obase];      // broadcast
            float4 wB = *(const float4*)&ws[cur][c][obase + 4];  // broadcast
            float2 wp[4];
            wp[0] = make_float2(wA.x, wA.y);
            wp[1] = make_float2(wA.z, wA.w);
            wp[2] = make_float2(wB.x, wB.y);
            wp[3] = make_float2(wB.z, wB.w);
#pragma unroll
            for (int op = 0; op < 4; op++)
#pragma unroll
                for (int p = 0; p < 4; p++)
                    acc[op][p] = ffma2(xd[p], wp[op], acc[op][p]);
        }
        __syncthreads();
    }
#pragma unroll
    for (int op = 0; op < 4; op++) {
        float* d0 = cb + (size_t)(obase + 2 * op) * HW + p0 + pl;
        *(float4*)d0 = make_float4(acc[op][0].x, acc[op][1].x,
                                   acc[op][2].x, acc[op][3].x);
        *(float4*)(d0 + HW) = make_float4(acc[op][0].y, acc[op][1].y,
                                          acc[op][2].y, acc[op][3].y);
    }
}

// ---------------------------------------------------------------------------
// Kernel 2: 3x3 conv (64->9) + bias + softmax, cp.async double-buffered.
// Pair dim = adjacent kk. Tile 64w x 8h, 256 thr, thread = 2 pixels.
// ---------------------------------------------------------------------------
__global__ void __launch_bounds__(256) k_convsoft(const float* __restrict__ wg,
                                                  const float* __restrict__ bg) {
    const int b  = blockIdx.z;
    const int h0 = blockIdx.y * 8;
    const int w0 = blockIdx.x * 64;

    __shared__ float xs[2][8][10][68];   // 2 x 21.8 KB
    __shared__ float wgs[2][8][9][12];   // 2 x 3.5 KB

    const int tid = threadIdx.x;
    const int lh  = tid >> 5;
    const int lw  = (tid & 31) * 2;

    const float* compb = g_comp + (size_t)b * COMP * HW;

    const uint32_t xs_base  = (uint32_t)__cvta_generic_to_shared(&xs[0][0][0][0]);
    const uint32_t wgs_base = (uint32_t)__cvta_generic_to_shared(&wgs[0][0][0][0]);

    auto stage = [&](int buf, int c0) {
        for (int idx = tid; idx < 8 * 9 * 12; idx += 256) {
            int c = idx / 108;
            int rem = idx - c * 108;
            int tap = rem / 12;
            int q = rem - tap * 12;
            const float* src = (q < 9) ? (wg + (q * COMP + c0 + c) * 9 + tap) : wg;
            cp_async4z(wgs_base + (uint32_t)(buf * 864 + idx) * 4, src,
                       (q < 9) ? 4 : 0);
        }
        for (int idx = tid; idx < 8 * 10 * 66; idx += 256) {
            int c = idx / 660;
            int rem = idx - c * 660;
            int r = rem / 66;
            int col = rem - r * 66;
            int gh = h0 + r - 1;
            int gw = w0 + col - 1;
            bool inb = ((unsigned)gh < 256u) && ((unsigned)gw < 256u);
            const float* src = inb ? (compb + (size_t)(c0 + c) * HW + gh * W + gw)
                                   : compb;
            cp_async4z(xs_base + (uint32_t)(buf * 8 * 10 * 68 + (c * 10 + r) * 68 + col) * 4,
                       src, inb ? 4 : 0);
        }
        CP_COMMIT();
    };

    float2 acc[2][5];
#pragma unroll
    for (int j = 0; j < 5; j++) {
        float blo = bg[2 * j];
        float bhi = (2 * j + 1 < 9) ? bg[2 * j + 1] : 0.f;
        acc[0][j] = make_float2(blo, bhi);
        acc[1][j] = make_float2(blo, bhi);
    }

    stage(0, 0);

    for (int it = 0; it < 8; it++) {
        const int cur = it & 1;
        if (it + 1 < 8) { stage(cur ^ 1, (it + 1) * 8); CP_WAIT(1); }
        else            { CP_WAIT(0); }
        __syncthreads();
#pragma unroll
        for (int c = 0; c < 8; c++) {
#pragma unroll
            for (int di = 0; di < 3; di++) {
                float2 a  = *(const float2*)&xs[cur][c][lh + di][lw];
                float2 b2 = *(const float2*)&xs[cur][c][lh + di][lw + 2];
                float2 d[4];
                d[0] = make_float2(a.x, a.x);
                d[1] = make_float2(a.y, a.y);
                d[2] = make_float2(b2.x, b2.x);
                d[3] = make_float2(b2.y, b2.y);
#pragma unroll
                for (int tap = 0; tap < 3; tap++) {
                    const float* wrow = &wgs[cur][c][di * 3 + tap][0];
                    float4 w0 = *(const float4*)(wrow);
                    float4 w1 = *(const float4*)(wrow + 4);
                    float4 w2 = *(const float4*)(wrow + 8);
                    float2 wq[5];
                    wq[0] = make_float2(w0.x, w0.y);
                    wq[1] = make_float2(w0.z, w0.w);
                    wq[2] = make_float2(w1.x, w1.y);
                    wq[3] = make_float2(w1.z, w1.w);
                    wq[4] = make_float2(w2.x, w2.y);
#pragma unroll
                    for (int j = 0; j < 5; j++) {
                        acc[0][j] = ffma2(d[tap],     wq[j], acc[0][j]);
                        acc[1][j] = ffma2(d[tap + 1], wq[j], acc[1][j]);
                    }
                }
            }
        }
        __syncthreads();
    }

    float v0[9], v1[9];
#pragma unroll
    for (int j = 0; j < 5; j++) {
        v0[2 * j] = acc[0][j].x;  v1[2 * j] = acc[1][j].x;
        if (2 * j + 1 < 9) { v0[2 * j + 1] = acc[0][j].y; v1[2 * j + 1] = acc[1][j].y; }
    }
    float mA = v0[0], mB = v1[0];
#pragma unroll
    for (int kk = 1; kk < 9; kk++) { mA = fmaxf(mA, v0[kk]); mB = fmaxf(mB, v1[kk]); }
    float sA = 0.f, sB = 0.f;
#pragma unroll
    for (int kk = 0; kk < 9; kk++) {
        v0[kk] = __expf(v0[kk] - mA); sA += v0[kk];
        v1[kk] = __expf(v1[kk] - mB); sB += v1[kk];
    }
    float iA = 1.f / sA, iB = 1.f / sB;
    float* sb = g_s + (size_t)b * 9 * HW;
    const int pbase = (h0 + lh) * W + w0 + lw;
#pragma unroll
    for (int kk = 0; kk < 9; kk++)
        *(float2*)(sb + (size_t)kk * HW + pbase) =
            make_float2(v0[kk] * iA, v1[kk] * iB);
}

// ---------------------------------------------------------------------------
// Kernel 3: per-pixel weights + reflect 3x3 aggregation. out = 2x - agg.
// Channel-split grid (64 ch/block), 3-deep cp.async pipeline.
// ---------------------------------------------------------------------------
#define K3_CH 8
#define K3_CHUNKS 8

__global__ void __launch_bounds__(256) k_aggregate(const float* __restrict__ x,
                                                   float* __restrict__ out) {
    const int bz = blockIdx.z;
    const int b  = bz >> 2;
    const int cg = bz & 3;
    const int h0 = blockIdx.y * 8;
    const int w0 = blockIdx.x * 64;

    __shared__ float xs[3][K3_CH][10][68];   // 3 x 21.8 KB

    const int tid = threadIdx.x;
    const int lh  = tid >> 5;
    const int lw  = (tid & 31) * 2;
    const int h = h0 + lh, wcol = w0 + lw;

    const float* xb = x + ((size_t)b * CIN + cg * 64) * HW;
    float* ob = out + ((size_t)b * CIN + cg * 64) * HW;

    const uint32_t smem_base =
        (uint32_t)__cvta_generic_to_shared(&xs[0][0][0][0]);

    auto stage = [&](int buf, int chunk) {
        const float* src_base = xb + (size_t)chunk * K3_CH * HW;
        uint32_t dbase = smem_base + buf * (K3_CH * 10 * 68 * 4);
        for (int idx = tid; idx < K3_CH * 10 * 66; idx += 256) {
            int c = idx / 660;
            int rem = idx - c * 660;
            int r = rem / 66;
            int col = rem - r * 66;
            int gh = h0 + r - 1;
            if (gh < 0) gh = -gh; else if (gh > 255) gh = 510 - gh;
            int gw = w0 + col - 1;
            if (gw < 0) gw = -gw; else if (gw > 255) gw = 510 - gw;
            cp_async4(dbase + (uint32_t)(((c * 10 + r) * 68 + col) * 4),
                      src_base + (size_t)c * HW + gh * W + gw);
        }
        CP_COMMIT();
    };

    stage(0, 0);
    stage(1, 1);

    // Per-pixel tap weights (gmem reads overlap the staged prefetches above)
    const float* sp = g_s + (size_t)b * 9 * HW + (size_t)(h * W + wcol) * 9;
    const float HAM[9] = {0.0064f, 0.08f, 0.0064f,
                          0.08f,   1.0f,  0.08f,
                          0.0064f, 0.08f, 0.0064f};
    float wa[9], wb[9];
    float sa = 0.f, sb = 0.f;
#pragma unroll
    for (int t = 0; t < 9; t++) {
        wa[t] = HAM[t] * sp[t];     sa += wa[t];
        wb[t] = HAM[t] * sp[9 + t]; sb += wb[t];
    }
    float ia = 1.f / (sa + 1e-8f);
    float ib = 1.f / (sb + 1e-8f);
    float2 wt2[9];
#pragma unroll
    for (int t = 0; t < 9; t++) wt2[t] = make_float2(wa[t] * ia, wb[t] * ib);

    for (int chunk = 0; chunk < K3_CHUNKS; chunk++) {
        const int cur = chunk % 3;
        if (chunk < K3_CHUNKS - 1) CP_WAIT(1);   // oldest group (cur) done
        else                       CP_WAIT(0);
        __syncthreads();

        float* ochunk = ob + (size_t)chunk * K3_CH * HW + h * W + wcol;
#pragma unroll
        for (int c = 0; c < K3_CH; c++) {
            float2 agg = make_float2(0.f, 0.f);
            float2 center = make_float2(0.f, 0.f);
#pragma unroll
            for (int di = 0; di < 3; di++) {
                float2 a  = *(const float2*)&xs[cur][c][lh + di][lw];
                float2 b2 = *(const float2*)&xs[cur][c][lh + di][lw + 2];
                float2 m  = make_float2(a.y, b2.x);
                agg = ffma2(a,  wt2[di * 3 + 0], agg);
                agg = ffma2(m,  wt2[di * 3 + 1], agg);
                agg = ffma2(b2, wt2[di * 3 + 2], agg);
                if (di == 1) center = m;
            }
            float2 o2 = make_float2(2.f * center.x - agg.x,
                                    2.f * center.y - agg.y);
            *(float2*)(ochunk + (size_t)c * HW) = o2;
        }
        __syncthreads();
        if (chunk + 2 < K3_CHUNKS) stage((chunk + 2) % 3, chunk + 2);
    }
}

// ---------------------------------------------------------------------------
extern "C" void kernel_launch(void* const* d_in, const int* in_sizes, int n_in,
                              void* d_out, int out_size) {
    const float* x  = (const float*)d_in[0];
    const float* wc = (const float*)d_in[1];
    const float* wg = (const float*)d_in[2];
    const float* bg = (const float*)d_in[3];
    float* out = (float*)d_out;

    k_wt       <<<64, 256>>>(wc);
    k_compress <<<dim3(HW / 128, BATCH), 256>>>(x);
    k_convsoft <<<dim3(W / 64, H / 8, BATCH), 256>>>(wg, bg);
    k_aggregate<<<dim3(W / 64, H / 8, BATCH * 4), 256>>>(x, out);
}

// round 6
// speedup vs baseline: 1.5584x; 1.0644x over previous
#include <cuda_runtime.h>
#include <cstdint>

#define H 256
#define W 256
#define CIN 256
#define COMP 64
#define BATCH 4
#define HW (H * W)

__device__ float g_comp[(size_t)BATCH * COMP * HW];   // 64 MiB
__device__ float g_s[(size_t)BATCH * 9 * HW];         // 9 MiB
__device__ float g_wt[CIN * COMP];                    // W transposed [c][o]

__device__ __forceinline__ float2 ffma2(float2 a, float2 b, float2 c) {
    unsigned long long au = *reinterpret_cast<unsigned long long*>(&a);
    unsigned long long bu = *reinterpret_cast<unsigned long long*>(&b);
    unsigned long long cu = *reinterpret_cast<unsigned long long*>(&c);
    unsigned long long du;
    asm("fma.rn.f32x2 %0, %1, %2, %3;" : "=l"(du) : "l"(au), "l"(bu), "l"(cu));
    return *reinterpret_cast<float2*>(&du);
}

__device__ __forceinline__ void cp_async16(uint32_t dst, const float* src) {
    asm volatile("cp.async.ca.shared.global [%0], [%1], 16;"
                 :: "r"(dst), "l"(src) : "memory");
}
__device__ __forceinline__ void cp_async4(uint32_t dst, const float* src) {
    asm volatile("cp.async.ca.shared.global [%0], [%1], 4;"
                 :: "r"(dst), "l"(src) : "memory");
}
__device__ __forceinline__ void cp_async16z(uint32_t dst, const float* src, int sz) {
    asm volatile("cp.async.ca.shared.global [%0], [%1], 16, %2;"
                 :: "r"(dst), "l"(src), "r"(sz) : "memory");
}
__device__ __forceinline__ void cp_async4z(uint32_t dst, const float* src, int sz) {
    asm volatile("cp.async.ca.shared.global [%0], [%1], 4, %2;"
                 :: "r"(dst), "l"(src), "r"(sz) : "memory");
}
#define CP_COMMIT() asm volatile("cp.async.commit_group;" ::: "memory")
#define CP_WAIT(n)  asm volatile("cp.async.wait_group %0;" :: "n"(n) : "memory")

// ---------------------------------------------------------------------------
// Kernel 0: transpose wc (64x256) -> g_wt (256x64)
// ---------------------------------------------------------------------------
__global__ void k_wt(const float* __restrict__ wc) {
    int e = blockIdx.x * 256 + threadIdx.x;
    int o = e >> 8, c = e & 255;
    g_wt[c * COMP + o] = wc[e];
}

// ---------------------------------------------------------------------------
// Kernel 1: 1x1 compression, cp.async double-buffered (unchanged from R5).
// ---------------------------------------------------------------------------
__global__ void __launch_bounds__(256) k_compress(const float* __restrict__ x) {
    const int b  = blockIdx.y;
    const int p0 = blockIdx.x * 128;
    const float* xb = x + (size_t)b * CIN * HW;
    float* cb = g_comp + (size_t)b * COMP * HW;

    __shared__ float ws[2][32][64];
    __shared__ float xs[2][32][128];

    const int tid   = threadIdx.x;
    const int lane  = tid & 31;
    const int warp  = tid >> 5;
    const int obase = warp * 8;
    const int pl    = lane * 4;

    const uint32_t ws_base = (uint32_t)__cvta_generic_to_shared(&ws[0][0][0]);
    const uint32_t xs_base = (uint32_t)__cvta_generic_to_shared(&xs[0][0][0]);

    auto stage = [&](int buf, int c0) {
#pragma unroll
        for (int i = 0; i < 4; i++) {
            int idx = tid + i * 256;
            int cc = idx >> 5;
            int k  = idx & 31;
            cp_async16(xs_base + (uint32_t)(buf * 32 * 128 + cc * 128 + k * 4) * 4,
                       xb + (size_t)(c0 + cc) * HW + p0 + k * 4);
        }
#pragma unroll
        for (int i = 0; i < 2; i++) {
            int idx = tid + i * 256;
            int cc = idx >> 4;
            int k  = idx & 15;
            cp_async16(ws_base + (uint32_t)(buf * 32 * 64 + cc * 64 + k * 4) * 4,
                       g_wt + (c0 + cc) * COMP + k * 4);
        }
        CP_COMMIT();
    };

    float2 acc[4][4];
#pragma unroll
    for (int op = 0; op < 4; op++)
#pragma unroll
        for (int p = 0; p < 4; p++) acc[op][p] = make_float2(0.f, 0.f);

    stage(0, 0);

    for (int it = 0; it < 8; it++) {
        const int cur = it & 1;
        if (it + 1 < 8) { stage(cur ^ 1, (it + 1) * 32); CP_WAIT(1); }
        else            { CP_WAIT(0); }
        __syncthreads();
#pragma unroll 4
        for (int c = 0; c < 32; c++) {
            float4 xv = *(const float4*)&xs[cur][c][pl];
            float2 xd[4];
            xd[0] = make_float2(xv.x, xv.x);
            xd[1] = make_float2(xv.y, xv.y);
            xd[2] = make_float2(xv.z, xv.z);
            xd[3] = make_float2(xv.w, xv.w);
            float4 wA = *(const float4*)&ws[cur][c][obase];
            float4 wB = *(const float4*)&ws[cur][c][obase + 4];
            float2 wp[4];
            wp[0] = make_float2(wA.x, wA.y);
            wp[1] = make_float2(wA.z, wA.w);
            wp[2] = make_float2(wB.x, wB.y);
            wp[3] = make_float2(wB.z, wB.w);
#pragma unroll
            for (int op = 0; op < 4; op++)
#pragma unroll
                for (int p = 0; p < 4; p++)
                    acc[op][p] = ffma2(xd[p], wp[op], acc[op][p]);
        }
        __syncthreads();
    }
#pragma unroll
    for (int op = 0; op < 4; op++) {
        float* d0 = cb + (size_t)(obase + 2 * op) * HW + p0 + pl;
        *(float4*)d0 = make_float4(acc[op][0].x, acc[op][1].x,
                                   acc[op][2].x, acc[op][3].x);
        *(float4*)(d0 + HW) = make_float4(acc[op][0].y, acc[op][1].y,
                                          acc[op][2].y, acc[op][3].y);
    }
}

// ---------------------------------------------------------------------------
// Kernel 2: 3x3 conv (64->9) + bias + softmax.
// Weights staged ONCE (all 64c); x staged 16B-wide with zero-fill, precomputed
// slots. smem row: idx i <-> gw = w0-4+i (stride 72).
// ---------------------------------------------------------------------------
__global__ void __launch_bounds__(256) k_convsoft(const float* __restrict__ wg,
                                                  const float* __restrict__ bg) {
    const int b  = blockIdx.z;
    const int h0 = blockIdx.y * 8;
    const int w0 = blockIdx.x * 64;

    __shared__ float xs[2][8][10][72];   // 2 x 23 KB
    __shared__ float wsAll[COMP][9][12]; // 27.6 KB

    const int tid = threadIdx.x;
    const int lh  = tid >> 5;
    const int lw  = (tid & 31) * 2;

    const float* compb = g_comp + (size_t)b * COMP * HW;

    const uint32_t xs_base  = (uint32_t)__cvta_generic_to_shared(&xs[0][0][0][0]);
    const uint32_t ws_base  = (uint32_t)__cvta_generic_to_shared(&wsAll[0][0][0]);

    // ---- stage ALL conv weights once (group A) ----
#pragma unroll
    for (int i = 0; i < 27; i++) {
        int idx = tid + i * 256;           // 6912 total
        if (idx < COMP * 9 * 12) {
            int c = idx / 108;
            int rem = idx - c * 108;
            int tap = rem / 12;
            int q = rem - tap * 12;
            const float* src = (q < 9) ? (wg + (q * COMP + c) * 9 + tap) : wg;
            cp_async4z(ws_base + (uint32_t)idx * 4, src, (q < 9) ? 4 : 0);
        }
    }
    CP_COMMIT();

    // ---- precompute x staging slots: 8c x 10r x 18k = 1440 ops ----
    int soff[6], goff[6], ssz[6];  // ssz: 16/4 = copy width, negative = zero-fill
    bool is16[6];
#pragma unroll
    for (int s = 0; s < 6; s++) {
        int idx = tid + s * 256;
        is16[s] = false; ssz[s] = -1;
        if (idx < 1440) {
            int c = idx / 180;
            int rem = idx - c * 180;
            int r = rem / 18;
            int k = rem - r * 18;
            int gh = h0 + r - 1;
            bool rowok = (unsigned)gh < 256u;
            int gw, dcol;
            bool colok = true;
            if (k < 16)      { gw = w0 + 4 * k; dcol = 4 + 4 * k; is16[s] = true; }
            else if (k == 16){ gw = w0 - 1;  dcol = 3;  colok = (gw >= 0); }
            else             { gw = w0 + 64; dcol = 68; colok = (gw <= 255); }
            bool ok = rowok && colok;
            if (!ok) { gh = 0; gw = 0; }
            soff[s] = ((c * 10 + r) * 72 + dcol) * 4;
            goff[s] = c * HW + gh * W + gw;
            ssz[s]  = ok ? (is16[s] ? 16 : 4) : 0;
        }
    }

    auto stage = [&](int buf, int c0) {
        const float* base = compb + (size_t)c0 * HW;
        uint32_t dbase = xs_base + (uint32_t)buf * (8 * 10 * 72 * 4);
#pragma unroll
        for (int s = 0; s < 6; s++) {
            if (ssz[s] < 0) continue;
            if (is16[s]) cp_async16z(dbase + soff[s], base + goff[s], ssz[s]);
            else         cp_async4z (dbase + soff[s], base + goff[s], ssz[s]);
        }
        CP_COMMIT();
    };

    float2 acc[2][5];
#pragma unroll
    for (int j = 0; j < 5; j++) {
        float blo = bg[2 * j];
        float bhi = (2 * j + 1 < 9) ? bg[2 * j + 1] : 0.f;
        acc[0][j] = make_float2(blo, bhi);
        acc[1][j] = make_float2(blo, bhi);
    }

    stage(0, 0);   // group B (chunk 0)

    for (int it = 0; it < 8; it++) {
        const int cur = it & 1;
        if (it + 1 < 8) { stage(cur ^ 1, (it + 1) * 8); CP_WAIT(1); }
        else            { CP_WAIT(0); }
        __syncthreads();
#pragma unroll
        for (int c = 0; c < 8; c++) {
            const int cg = it * 8 + c;
#pragma unroll
            for (int di = 0; di < 3; di++) {
                float2 A = *(const float2*)&xs[cur][c][lh + di][lw + 2];
                float2 B = *(const float2*)&xs[cur][c][lh + di][lw + 4];
                float  C = xs[cur][c][lh + di][lw + 6];
                float2 d[4];
                d[0] = make_float2(A.y, A.y);
                d[1] = make_float2(B.x, B.x);
                d[2] = make_float2(B.y, B.y);
                d[3] = make_float2(C,   C);
#pragma unroll
                for (int tap = 0; tap < 3; tap++) {
                    const float* wrow = &wsAll[cg][di * 3 + tap][0];
                    float4 w0v = *(const float4*)(wrow);
                    float4 w1v = *(const float4*)(wrow + 4);
                    float4 w2v = *(const float4*)(wrow + 8);
                    float2 wq[5];
                    wq[0] = make_float2(w0v.x, w0v.y);
                    wq[1] = make_float2(w0v.z, w0v.w);
                    wq[2] = make_float2(w1v.x, w1v.y);
                    wq[3] = make_float2(w1v.z, w1v.w);
                    wq[4] = make_float2(w2v.x, w2v.y);
#pragma unroll
                    for (int j = 0; j < 5; j++) {
                        acc[0][j] = ffma2(d[tap],     wq[j], acc[0][j]);
                        acc[1][j] = ffma2(d[tap + 1], wq[j], acc[1][j]);
                    }
                }
            }
        }
        __syncthreads();
    }

    float v0[9], v1[9];
#pragma unroll
    for (int j = 0; j < 5; j++) {
        v0[2 * j] = acc[0][j].x;  v1[2 * j] = acc[1][j].x;
        if (2 * j + 1 < 9) { v0[2 * j + 1] = acc[0][j].y; v1[2 * j + 1] = acc[1][j].y; }
    }
    float mA = v0[0], mB = v1[0];
#pragma unroll
    for (int kk = 1; kk < 9; kk++) { mA = fmaxf(mA, v0[kk]); mB = fmaxf(mB, v1[kk]); }
    float sA = 0.f, sB = 0.f;
#pragma unroll
    for (int kk = 0; kk < 9; kk++) {
        v0[kk] = __expf(v0[kk] - mA); sA += v0[kk];
        v1[kk] = __expf(v1[kk] - mB); sB += v1[kk];
    }
    float iA = 1.f / sA, iB = 1.f / sB;
    float* sb = g_s + (size_t)b * 9 * HW;
    const int pbase = (h0 + lh) * W + w0 + lw;
#pragma unroll
    for (int kk = 0; kk < 9; kk++)
        *(float2*)(sb + (size_t)kk * HW + pbase) =
            make_float2(v0[kk] * iA, v1[kk] * iB);
}

// ---------------------------------------------------------------------------
// Kernel 3: per-pixel weights + reflect 3x3 aggregation. out = 2x - agg.
// 16B staging + precomputed slots + 3-deep cp.async pipeline.
// smem row: idx i <-> gw = w0-4+i (stride 72).
// ---------------------------------------------------------------------------
#define K3_CH 8
#define K3_CHUNKS 8

__global__ void __launch_bounds__(256, 3) k_aggregate(const float* __restrict__ x,
                                                      float* __restrict__ out) {
    const int bz = blockIdx.z;
    const int b  = bz >> 2;
    const int cg = bz & 3;
    const int h0 = blockIdx.y * 8;
    const int w0 = blockIdx.x * 64;

    __shared__ float xs[3][K3_CH][10][72];   // 3 x 23 KB

    const int tid = threadIdx.x;
    const int lh  = tid >> 5;
    const int lw  = (tid & 31) * 2;
    const int h = h0 + lh, wcol = w0 + lw;

    const float* xb = x + ((size_t)b * CIN + cg * 64) * HW;
    float* ob = out + ((size_t)b * CIN + cg * 64) * HW;

    const uint32_t smem_base =
        (uint32_t)__cvta_generic_to_shared(&xs[0][0][0][0]);

    // ---- precompute staging slots: 8c x 10r x 18k = 1440 ops ----
    int soff[6], goff[6];
    bool is16[6], valid[6];
#pragma unroll
    for (int s = 0; s < 6; s++) {
        int idx = tid + s * 256;
        valid[s] = (idx < 1440);
        is16[s] = false;
        if (valid[s]) {
            int c = idx / 180;
            int rem = idx - c * 180;
            int r = rem / 18;
            int k = rem - r * 18;
            int gh = h0 + r - 1;
            if (gh < 0) gh = -gh; else if (gh > 255) gh = 510 - gh;   // reflect
            int gw, dcol;
            if (k < 16)      { gw = w0 + 4 * k; dcol = 4 + 4 * k; is16[s] = true; }
            else if (k == 16){ gw = w0 - 1;  if (gw < 0) gw = 1;          dcol = 3; }
            else             { gw = w0 + 64; if (gw > 255) gw = 510 - gw; dcol = 68; }
            soff[s] = ((c * 10 + r) * 72 + dcol) * 4;
            goff[s] = c * HW + gh * W + gw;
        }
    }

    auto stage = [&](int buf, int chunk) {
        const float* base = xb + (size_t)chunk * K3_CH * HW;
        uint32_t dbase = smem_base + (uint32_t)buf * (K3_CH * 10 * 72 * 4);
#pragma unroll
        for (int s = 0; s < 6; s++) {
            if (!valid[s]) continue;
            if (is16[s]) cp_async16(dbase + soff[s], base + goff[s]);
            else         cp_async4 (dbase + soff[s], base + goff[s]);
        }
        CP_COMMIT();
    };

    stage(0, 0);
    stage(1, 1);

    // Per-pixel tap weights (overlaps the prefetches above)
    const float* sp = g_s + (size_t)b * 9 * HW + (size_t)(h * W + wcol) * 9;
    const float HAM[9] = {0.0064f, 0.08f, 0.0064f,
                          0.08f,   1.0f,  0.08f,
                          0.0064f, 0.08f, 0.0064f};
    float wa[9], wb[9];
    float sa = 0.f, sb = 0.f;
#pragma unroll
    for (int t = 0; t < 9; t++) {
        wa[t] = HAM[t] * sp[t];     sa += wa[t];
        wb[t] = HAM[t] * sp[9 + t]; sb += wb[t];
    }
    float ia = 1.f / (sa + 1e-8f);
    float ib = 1.f / (sb + 1e-8f);
    float2 wt2[9];
#pragma unroll
    for (int t = 0; t < 9; t++) wt2[t] = make_float2(wa[t] * ia, wb[t] * ib);

    for (int chunk = 0; chunk < K3_CHUNKS; chunk++) {
        const int cur = chunk % 3;
        if (chunk < K3_CHUNKS - 1) CP_WAIT(1);
        else                       CP_WAIT(0);
        __syncthreads();

        float* ochunk = ob + (size_t)chunk * K3_CH * HW + h * W + wcol;
#pragma unroll
        for (int c = 0; c < K3_CH; c++) {
            float2 agg = make_float2(0.f, 0.f);
            float2 center = make_float2(0.f, 0.f);
#pragma unroll
            for (int di = 0; di < 3; di++) {
                float2 A = *(const float2*)&xs[cur][c][lh + di][lw + 2];
                float2 B = *(const float2*)&xs[cur][c][lh + di][lw + 4];
                float  C = xs[cur][c][lh + di][lw + 6];
                float2 t0 = make_float2(A.y, B.x);
                float2 t2 = make_float2(B.y, C);
                agg = ffma2(t0, wt2[di * 3 + 0], agg);
                agg = ffma2(B,  wt2[di * 3 + 1], agg);
                agg = ffma2(t2, wt2[di * 3 + 2], agg);
                if (di == 1) center = B;
            }
            float2 o2 = make_float2(2.f * center.x - agg.x,
                                    2.f * center.y - agg.y);
            *(float2*)(ochunk + (size_t)c * HW) = o2;
        }
        __syncthreads();
        if (chunk + 2 < K3_CHUNKS) stage((chunk + 2) % 3, chunk + 2);
    }
}

// ---------------------------------------------------------------------------
extern "C" void kernel_launch(void* const* d_in, const int* in_sizes, int n_in,
                              void* d_out, int out_size) {
    const float* x  = (const float*)d_in[0];
    const float* wc = (const float*)d_in[1];
    const float* wg = (const float*)d_in[2];
    const float* bg = (const float*)d_in[3];
    float* out = (float*)d_out;

    k_wt       <<<64, 256>>>(wc);
    k_compress <<<dim3(HW / 128, BATCH), 256>>>(x);
    k_convsoft <<<dim3(W / 64, H / 8, BATCH), 256>>>(wg, bg);
    k_aggregate<<<dim3(W / 64, H / 8, BATCH * 4), 256>>>(x, out);
}

// round 7
// speedup vs baseline: 1.7059x; 1.0946x over previous
#include <cuda_runtime.h>
#include <cstdint>

#define H 256
#define W 256
#define CIN 256
#define COMP 64
#define BATCH 4
#define HW (H * W)

__device__ float g_comp[(size_t)BATCH * COMP * HW];   // 64 MiB
__device__ float g_s[(size_t)BATCH * 9 * HW];         // 9 MiB
__device__ float g_wt[CIN * COMP];                    // W transposed [c][o]

__device__ __forceinline__ float2 ffma2(float2 a, float2 b, float2 c) {
    unsigned long long au = *reinterpret_cast<unsigned long long*>(&a);
    unsigned long long bu = *reinterpret_cast<unsigned long long*>(&b);
    unsigned long long cu = *reinterpret_cast<unsigned long long*>(&c);
    unsigned long long du;
    asm("fma.rn.f32x2 %0, %1, %2, %3;" : "=l"(du) : "l"(au), "l"(bu), "l"(cu));
    return *reinterpret_cast<float2*>(&du);
}

__device__ __forceinline__ void cp_async16(uint32_t dst, const float* src) {
    asm volatile("cp.async.ca.shared.global [%0], [%1], 16;"
                 :: "r"(dst), "l"(src) : "memory");
}
__device__ __forceinline__ void cp_async16z(uint32_t dst, const float* src, int sz) {
    asm volatile("cp.async.ca.shared.global [%0], [%1], 16, %2;"
                 :: "r"(dst), "l"(src), "r"(sz) : "memory");
}
__device__ __forceinline__ void cp_async4z(uint32_t dst, const float* src, int sz) {
    asm volatile("cp.async.ca.shared.global [%0], [%1], 4, %2;"
                 :: "r"(dst), "l"(src), "r"(sz) : "memory");
}
#define CP_COMMIT() asm volatile("cp.async.commit_group;" ::: "memory")
#define CP_WAIT(n)  asm volatile("cp.async.wait_group %0;" :: "n"(n) : "memory")

// ---------------------------------------------------------------------------
// Kernel 0: transpose wc (64x256) -> g_wt (256x64)
// ---------------------------------------------------------------------------
__global__ void k_wt(const float* __restrict__ wc) {
    int e = blockIdx.x * 256 + threadIdx.x;
    int o = e >> 8, c = e & 255;
    g_wt[c * COMP + o] = wc[e];
}

// ---------------------------------------------------------------------------
// Kernel 1: 1x1 compression, cp.async double-buffered (unchanged).
// ---------------------------------------------------------------------------
__global__ void __launch_bounds__(256) k_compress(const float* __restrict__ x) {
    const int b  = blockIdx.y;
    const int p0 = blockIdx.x * 128;
    const float* xb = x + (size_t)b * CIN * HW;
    float* cb = g_comp + (size_t)b * COMP * HW;

    __shared__ float ws[2][32][64];
    __shared__ float xs[2][32][128];

    const int tid   = threadIdx.x;
    const int lane  = tid & 31;
    const int warp  = tid >> 5;
    const int obase = warp * 8;
    const int pl    = lane * 4;

    const uint32_t ws_base = (uint32_t)__cvta_generic_to_shared(&ws[0][0][0]);
    const uint32_t xs_base = (uint32_t)__cvta_generic_to_shared(&xs[0][0][0]);

    auto stage = [&](int buf, int c0) {
#pragma unroll
        for (int i = 0; i < 4; i++) {
            int idx = tid + i * 256;
            int cc = idx >> 5;
            int k  = idx & 31;
            cp_async16(xs_base + (uint32_t)(buf * 32 * 128 + cc * 128 + k * 4) * 4,
                       xb + (size_t)(c0 + cc) * HW + p0 + k * 4);
        }
#pragma unroll
        for (int i = 0; i < 2; i++) {
            int idx = tid + i * 256;
            int cc = idx >> 4;
            int k  = idx & 15;
            cp_async16(ws_base + (uint32_t)(buf * 32 * 64 + cc * 64 + k * 4) * 4,
                       g_wt + (c0 + cc) * COMP + k * 4);
        }
        CP_COMMIT();
    };

    float2 acc[4][4];
#pragma unroll
    for (int op = 0; op < 4; op++)
#pragma unroll
        for (int p = 0; p < 4; p++) acc[op][p] = make_float2(0.f, 0.f);

    stage(0, 0);

    for (int it = 0; it < 8; it++) {
        const int cur = it & 1;
        if (it + 1 < 8) { stage(cur ^ 1, (it + 1) * 32); CP_WAIT(1); }
        else            { CP_WAIT(0); }
        __syncthreads();
#pragma unroll 4
        for (int c = 0; c < 32; c++) {
            float4 xv = *(const float4*)&xs[cur][c][pl];
            float2 xd[4];
            xd[0] = make_float2(xv.x, xv.x);
            xd[1] = make_float2(xv.y, xv.y);
            xd[2] = make_float2(xv.z, xv.z);
            xd[3] = make_float2(xv.w, xv.w);
            float4 wA = *(const float4*)&ws[cur][c][obase];
            float4 wB = *(const float4*)&ws[cur][c][obase + 4];
            float2 wp[4];
            wp[0] = make_float2(wA.x, wA.y);
            wp[1] = make_float2(wA.z, wA.w);
            wp[2] = make_float2(wB.x, wB.y);
            wp[3] = make_float2(wB.z, wB.w);
#pragma unroll
            for (int op = 0; op < 4; op++)
#pragma unroll
                for (int p = 0; p < 4; p++)
                    acc[op][p] = ffma2(xd[p], wp[op], acc[op][p]);
        }
        __syncthreads();
    }
#pragma unroll
    for (int op = 0; op < 4; op++) {
        float* d0 = cb + (size_t)(obase + 2 * op) * HW + p0 + pl;
        *(float4*)d0 = make_float4(acc[op][0].x, acc[op][1].x,
                                   acc[op][2].x, acc[op][3].x);
        *(float4*)(d0 + HW) = make_float4(acc[op][0].y, acc[op][1].y,
                                          acc[op][2].y, acc[op][3].y);
    }
}

// ---------------------------------------------------------------------------
// Kernel 2: 3x3 conv (64->9) + bias + softmax (unchanged from R6).
// ---------------------------------------------------------------------------
__global__ void __launch_bounds__(256) k_convsoft(const float* __restrict__ wg,
                                                  const float* __restrict__ bg) {
    const int b  = blockIdx.z;
    const int h0 = blockIdx.y * 8;
    const int w0 = blockIdx.x * 64;

    __shared__ float xs[2][8][10][72];
    __shared__ float wsAll[COMP][9][12];

    const int tid = threadIdx.x;
    const int lh  = tid >> 5;
    const int lw  = (tid & 31) * 2;

    const float* compb = g_comp + (size_t)b * COMP * HW;

    const uint32_t xs_base  = (uint32_t)__cvta_generic_to_shared(&xs[0][0][0][0]);
    const uint32_t ws_base  = (uint32_t)__cvta_generic_to_shared(&wsAll[0][0][0]);

#pragma unroll
    for (int i = 0; i < 27; i++) {
        int idx = tid + i * 256;
        if (idx < COMP * 9 * 12) {
            int c = idx / 108;
            int rem = idx - c * 108;
            int tap = rem / 12;
            int q = rem - tap * 12;
            const float* src = (q < 9) ? (wg + (q * COMP + c) * 9 + tap) : wg;
            cp_async4z(ws_base + (uint32_t)idx * 4, src, (q < 9) ? 4 : 0);
        }
    }
    CP_COMMIT();

    int soff[6], goff[6], ssz[6];
    bool is16[6];
#pragma unroll
    for (int s = 0; s < 6; s++) {
        int idx = tid + s * 256;
        is16[s] = false; ssz[s] = -1;
        if (idx < 1440) {
            int c = idx / 180;
            int rem = idx - c * 180;
            int r = rem / 18;
            int k = rem - r * 18;
            int gh = h0 + r - 1;
            bool rowok = (unsigned)gh < 256u;
            int gw, dcol;
            bool colok = true;
            if (k < 16)      { gw = w0 + 4 * k; dcol = 4 + 4 * k; is16[s] = true; }
            else if (k == 16){ gw = w0 - 1;  dcol = 3;  colok = (gw >= 0); }
            else             { gw = w0 + 64; dcol = 68; colok = (gw <= 255); }
            bool ok = rowok && colok;
            if (!ok) { gh = 0; gw = 0; }
            soff[s] = ((c * 10 + r) * 72 + dcol) * 4;
            goff[s] = c * HW + gh * W + gw;
            ssz[s]  = ok ? (is16[s] ? 16 : 4) : 0;
        }
    }

    auto stage = [&](int buf, int c0) {
        const float* base = compb + (size_t)c0 * HW;
        uint32_t dbase = xs_base + (uint32_t)buf * (8 * 10 * 72 * 4);
#pragma unroll
        for (int s = 0; s < 6; s++) {
            if (ssz[s] < 0) continue;
            if (is16[s]) cp_async16z(dbase + soff[s], base + goff[s], ssz[s]);
            else         cp_async4z (dbase + soff[s], base + goff[s], ssz[s]);
        }
        CP_COMMIT();
    };

    float2 acc[2][5];
#pragma unroll
    for (int j = 0; j < 5; j++) {
        float blo = bg[2 * j];
        float bhi = (2 * j + 1 < 9) ? bg[2 * j + 1] : 0.f;
        acc[0][j] = make_float2(blo, bhi);
        acc[1][j] = make_float2(blo, bhi);
    }

    stage(0, 0);

    for (int it = 0; it < 8; it++) {
        const int cur = it & 1;
        if (it + 1 < 8) { stage(cur ^ 1, (it + 1) * 8); CP_WAIT(1); }
        else            { CP_WAIT(0); }
        __syncthreads();
#pragma unroll
        for (int c = 0; c < 8; c++) {
            const int cg = it * 8 + c;
#pragma unroll
            for (int di = 0; di < 3; di++) {
                float2 A = *(const float2*)&xs[cur][c][lh + di][lw + 2];
                float2 B = *(const float2*)&xs[cur][c][lh + di][lw + 4];
                float  C = xs[cur][c][lh + di][lw + 6];
                float2 d[4];
                d[0] = make_float2(A.y, A.y);
                d[1] = make_float2(B.x, B.x);
                d[2] = make_float2(B.y, B.y);
                d[3] = make_float2(C,   C);
#pragma unroll
                for (int tap = 0; tap < 3; tap++) {
                    const float* wrow = &wsAll[cg][di * 3 + tap][0];
                    float4 w0v = *(const float4*)(wrow);
                    float4 w1v = *(const float4*)(wrow + 4);
                    float4 w2v = *(const float4*)(wrow + 8);
                    float2 wq[5];
                    wq[0] = make_float2(w0v.x, w0v.y);
                    wq[1] = make_float2(w0v.z, w0v.w);
                    wq[2] = make_float2(w1v.x, w1v.y);
                    wq[3] = make_float2(w1v.z, w1v.w);
                    wq[4] = make_float2(w2v.x, w2v.y);
#pragma unroll
                    for (int j = 0; j < 5; j++) {
                        acc[0][j] = ffma2(d[tap],     wq[j], acc[0][j]);
                        acc[1][j] = ffma2(d[tap + 1], wq[j], acc[1][j]);
                    }
                }
            }
        }
        __syncthreads();
    }

    float v0[9], v1[9];
#pragma unroll
    for (int j = 0; j < 5; j++) {
        v0[2 * j] = acc[0][j].x;  v1[2 * j] = acc[1][j].x;
        if (2 * j + 1 < 9) { v0[2 * j + 1] = acc[0][j].y; v1[2 * j + 1] = acc[1][j].y; }
    }
    float mA = v0[0], mB = v1[0];
#pragma unroll
    for (int kk = 1; kk < 9; kk++) { mA = fmaxf(mA, v0[kk]); mB = fmaxf(mB, v1[kk]); }
    float sA = 0.f, sB = 0.f;
#pragma unroll
    for (int kk = 0; kk < 9; kk++) {
        v0[kk] = __expf(v0[kk] - mA); sA += v0[kk];
        v1[kk] = __expf(v1[kk] - mB); sB += v1[kk];
    }
    float iA = 1.f / sA, iB = 1.f / sB;
    float* sb = g_s + (size_t)b * 9 * HW;
    const int pbase = (h0 + lh) * W + w0 + lw;
#pragma unroll
    for (int kk = 0; kk < 9; kk++)
        *(float2*)(sb + (size_t)kk * HW + pbase) =
            make_float2(v0[kk] * iA, v1[kk] * iB);
}

// ---------------------------------------------------------------------------
// Kernel 3: direct-gmem 3x3 weighted aggregation. out = 2x - agg.
// Thread = 4 consecutive px (float4) at one h; no smem, no barriers.
// Row reuse via L1 (adjacent lh warps), tile boundaries via L2.
// ---------------------------------------------------------------------------
__global__ void __launch_bounds__(256, 2) k_aggregate(const float* __restrict__ x,
                                                      float* __restrict__ out) {
    const int bz = blockIdx.z;
    const int b  = bz >> 2;
    const int cg = bz & 3;
    const int h0 = blockIdx.y * 8;
    const int w0 = blockIdx.x * 128;

    const int tid = threadIdx.x;
    const int lh  = tid >> 5;
    const int w   = w0 + (tid & 31) * 4;
    const int h   = h0 + lh;

    // ---- per-pixel tap weights for 4 pixels ----
    const float* sp = g_s + (size_t)b * 9 * HW + (size_t)(h * W + w) * 9;
    const float HAM[9] = {0.0064f, 0.08f, 0.0064f,
                          0.08f,   1.0f,  0.08f,
                          0.0064f, 0.08f, 0.0064f};
    float wv[4][9];
#pragma unroll
    for (int p = 0; p < 4; p++) {
        float s = 0.f;
#pragma unroll
        for (int t = 0; t < 9; t++) { wv[p][t] = HAM[t] * sp[p * 9 + t]; s += wv[p][t]; }
        float inv = 1.f / (s + 1e-8f);
#pragma unroll
        for (int t = 0; t < 9; t++) wv[p][t] *= inv;
    }
    float2 wA[9], wB[9];
#pragma unroll
    for (int t = 0; t < 9; t++) {
        wA[t] = make_float2(wv[0][t], wv[1][t]);
        wB[t] = make_float2(wv[2][t], wv[3][t]);
    }

    // reflect-padded row/col offsets (constant over channel loop)
    const int hm = (h == 0)   ? 1   : h - 1;
    const int hp = (h == 255) ? 254 : h + 1;
    const int wl = (w == 0)   ? 1   : w - 1;
    const int wr = (w + 4 > 255) ? 254 : w + 4;
    const int rm = hm * W, r0 = h * W, rp = hp * W;

    const float* xb = x  + ((size_t)b * CIN + cg * 64) * HW;
    float*       ob = out + ((size_t)b * CIN + cg * 64) * HW;

#pragma unroll 2
    for (int c = 0; c < 64; c++) {
        const float* pc = xb + (size_t)c * HW;
        float4 Bm = *(const float4*)(pc + rm + w);
        float  Lm = pc[rm + wl], Rm = pc[rm + wr];
        float4 B0 = *(const float4*)(pc + r0 + w);
        float  L0 = pc[r0 + wl], R0 = pc[r0 + wr];
        float4 Bp = *(const float4*)(pc + rp + w);
        float  Lp = pc[rp + wl], Rp = pc[rp + wr];

        float2 aggA = make_float2(0.f, 0.f);
        float2 aggB = make_float2(0.f, 0.f);
        // row h-1: taps 0,1,2
        aggA = ffma2(make_float2(Lm,  Bm.x), wA[0], aggA);
        aggA = ffma2(make_float2(Bm.x, Bm.y), wA[1], aggA);
        aggA = ffma2(make_float2(Bm.y, Bm.z), wA[2], aggA);
        aggB = ffma2(make_float2(Bm.y, Bm.z), wB[0], aggB);
        aggB = ffma2(make_float2(Bm.z, Bm.w), wB[1], aggB);
        aggB = ffma2(make_float2(Bm.w, Rm),   wB[2], aggB);
        // row h: taps 3,4,5
        aggA = ffma2(make_float2(L0,  B0.x), wA[3], aggA);
        aggA = ffma2(make_float2(B0.x, B0.y), wA[4], aggA);
        aggA = ffma2(make_float2(B0.y, B0.z), wA[5], aggA);
        aggB = ffma2(make_float2(B0.y, B0.z), wB[3], aggB);
        aggB = ffma2(make_float2(B0.z, B0.w), wB[4], aggB);
        aggB = ffma2(make_float2(B0.w, R0),   wB[5], aggB);
        // row h+1: taps 6,7,8
        aggA = ffma2(make_float2(Lp,  Bp.x), wA[6], aggA);
        aggA = ffma2(make_float2(Bp.x, Bp.y), wA[7], aggA);
        aggA = ffma2(make_float2(Bp.y, Bp.z), wA[8], aggA);
        aggB = ffma2(make_float2(Bp.y, Bp.z), wB[6], aggB);
        aggB = ffma2(make_float2(Bp.z, Bp.w), wB[7], aggB);
        aggB = ffma2(make_float2(Bp.w, Rp),   wB[8], aggB);

        float4 o4;
        o4.x = 2.f * B0.x - aggA.x;
        o4.y = 2.f * B0.y - aggA.y;
        o4.z = 2.f * B0.z - aggB.x;
        o4.w = 2.f * B0.w - aggB.y;
        *(float4*)(ob + (size_t)c * HW + r0 + w) = o4;
    }
}

// ---------------------------------------------------------------------------
extern "C" void kernel_launch(void* const* d_in, const int* in_sizes, int n_in,
                              void* d_out, int out_size) {
    const float* x  = (const float*)d_in[0];
    const float* wc = (const float*)d_in[1];
    const float* wg = (const float*)d_in[2];
    const float* bg = (const float*)d_in[3];
    float* out = (float*)d_out;

    k_wt       <<<64, 256>>>(wc);
    k_compress <<<dim3(HW / 128, BATCH), 256>>>(x);
    k_convsoft <<<dim3(W / 64, H / 8, BATCH), 256>>>(wg, bg);
    k_aggregate<<<dim3(W / 128, H / 8, BATCH * 4), 256>>>(x, out);
}